// round 14
// baseline (speedup 1.0000x reference)
#include <cuda_runtime.h>

// VectorQuantizer: z [32768, 64] fp32, codebook [1024, 64] fp32.
// Outputs (float32, concatenated): z_q (2097152) | loss (1) | indices (32768).
//
// d2_k = fl( fl(znorm + cnorm_k) - fl(2 * dot_k) )  -- replicates reference
// rounding composition so argmin matches jnp.argmin (first-min tie-break).
//
// vq_kernel = exact 137us R13 form (R4 loop + register prefetch of next code
// tile). This round: loss_kernel and noop_kernel removed; loss is reduced
// across blocks inside vq via a DETERMINISTIC fixed-point integer atomic
// (2^20 scale, exact double conversion) + ticket-elected finalizer that also
// resets state for the next graph replay.

#define NROWS    32768
#define DIM      64
#define KCODES   1024
#define TM       64          // rows per block
#define TN       64          // codes per tile
#define NTILES   (KCODES / TN)
#define NTHREADS 256
#define NBLOCKS  (NROWS / TM)
#define ZS       68          // smem stride (floats), mult of 4 for float4 align
#define CS       68

typedef unsigned long long ull;

__device__ __align__(16) float g_cnorm[KCODES];
__device__ ull          g_loss_acc = 0ULL;   // fixed-point sum, 2^20 scale
__device__ unsigned int g_ticket   = 0u;     // completion ticket

__device__ __forceinline__ ull pack2dup(float x) {
    ull r; asm("mov.b64 %0, {%1, %1};" : "=l"(r) : "f"(x)); return r;
}
__device__ __forceinline__ void fma2(ull& acc, ull a, ull b) {
    asm("fma.rn.f32x2 %0, %1, %2, %0;" : "+l"(acc) : "l"(a), "l"(b));
}
__device__ __forceinline__ void unpack2(ull v, float& lo, float& hi) {
    asm("mov.b64 {%0, %1}, %2;" : "=f"(lo), "=f"(hi) : "l"(v));
}

// ---------------------------------------------------------------------------
// Kernel 1: codebook row norms (verified fast version: MLP-16 float4 loads,
// sequential fp32 adds in ascending element order -- same rounding as the
// square-then-sum reference).
// ---------------------------------------------------------------------------
__global__ void cnorm_kernel(const float* __restrict__ cb) {
    int k = blockIdx.x * 64 + threadIdx.x;
    const float4* row = (const float4*)(cb + k * DIM);
    float4 v[16];
#pragma unroll
    for (int i = 0; i < 16; i++) v[i] = __ldg(row + i);
    float s = 0.0f;
#pragma unroll
    for (int i = 0; i < 16; i++) {
        s = __fadd_rn(s, __fmul_rn(v[i].x, v[i].x));
        s = __fadd_rn(s, __fmul_rn(v[i].y, v[i].y));
        s = __fadd_rn(s, __fmul_rn(v[i].z, v[i].z));
        s = __fadd_rn(s, __fmul_rn(v[i].w, v[i].w));
    }
    g_cnorm[k] = s;
}

// ---------------------------------------------------------------------------
// Kernel 2: main VQ (R13 form: R4 loop + register prefetch of next tile).
// Each block: 64 rows x 1024 codes. Thread (tx, ty): rows ty*4..ty*4+3,
// codes {tile*64 + tx*4 + 0..3}. f32x2 packed FMA: z row-pairs native in
// transposed smem; c duplicated into both halves via pack2dup.
// Tail: deterministic fixed-point loss accumulation + ticket finalizer.
// ---------------------------------------------------------------------------
__global__ __launch_bounds__(NTHREADS, 4)
void vq_kernel(const float* __restrict__ z,
               const float* __restrict__ codebook,
               float* __restrict__ out) {
    __shared__ float zsT[DIM * ZS];     // zsT[d][r]
    __shared__ float csT[DIM * CS];     // csT[d][c_local]
    __shared__ float znorm_s[TM];
    __shared__ int   ridx_s[TM];
    __shared__ float lsum_s[16];

    const int tid = threadIdx.x;
    const int tx = tid & 15;            // code group
    const int ty = tid >> 4;            // row group
    const int rowBase = blockIdx.x * TM;

    // loader coordinates: each thread owns dim dd of codes {4i + c0l}
    const int dd  = tid & 63;
    const int c0l = tid >> 6;

    // ---- load z tile (coalesced), store transposed ----
    #pragma unroll
    for (int i = 0; i < 16; i++) {
        int flat = i * NTHREADS + tid;
        int r = flat >> 6, d = flat & 63;
        zsT[d * ZS + r] = z[(rowBase + r) * DIM + d];
    }

    // ---- prefetch code tile 0 into registers (overlaps znorm phase) ----
    float pf[16];
    #pragma unroll
    for (int i = 0; i < 16; i++)
        pf[i] = __ldg(codebook + (4 * i + c0l) * DIM + dd);

    __syncthreads();

    // ---- row norms: square (rounded) then sequential add ----
    if (tid < TM) {
        float s = 0.0f;
        #pragma unroll
        for (int k = 0; k < DIM; k++) {
            float v = zsT[k * ZS + tid];
            s = __fadd_rn(s, __fmul_rn(v, v));
        }
        znorm_s[tid] = s;
    }
    __syncthreads();

    float zn[4];
    #pragma unroll
    for (int r = 0; r < 4; r++) zn[r] = znorm_s[(ty << 2) + r];

    float minval[4] = {3.4e38f, 3.4e38f, 3.4e38f, 3.4e38f};
    int   minidx[4] = {0, 0, 0, 0};

    for (int t = 0; t < NTILES; t++) {
        const int cbase = t * TN;

        // ---- store prefetched tile (same addresses as R4 loader) ----
        #pragma unroll
        for (int i = 0; i < 16; i++)
            csT[dd * CS + 4 * i + c0l] = pf[i];
        __syncthreads();

        // ---- issue next tile's loads; consumed after the k-loop ----
        if (t + 1 < NTILES) {
            const float* src = codebook + (cbase + TN) * DIM;
            #pragma unroll
            for (int i = 0; i < 16; i++)
                pf[i] = __ldg(src + (4 * i + c0l) * DIM + dd);
        }

        // acc[rp][c]: rp=0 -> rows (0,1) packed, rp=1 -> rows (2,3) packed
        ull acc[2][4];
        #pragma unroll
        for (int rp = 0; rp < 2; rp++)
            #pragma unroll
            for (int c = 0; c < 4; c++) acc[rp][c] = 0ull;  // {0.f, 0.f}

        #pragma unroll 8
        for (int k = 0; k < DIM; k++) {
            const ull* zp = (const ull*)&zsT[k * ZS + (ty << 2)];
            ull z01 = zp[0];           // {z[row0], z[row1]}
            ull z23 = zp[1];           // {z[row2], z[row3]}
            float4 cv = *(const float4*)&csT[k * CS + (tx << 2)];
            ull c0 = pack2dup(cv.x);
            ull c1 = pack2dup(cv.y);
            ull c2 = pack2dup(cv.z);
            ull c3 = pack2dup(cv.w);
            fma2(acc[0][0], z01, c0); fma2(acc[1][0], z23, c0);
            fma2(acc[0][1], z01, c1); fma2(acc[1][1], z23, c1);
            fma2(acc[0][2], z01, c2); fma2(acc[1][2], z23, c2);
            fma2(acc[0][3], z01, c3); fma2(acc[1][3], z23, c3);
        }

        // epilogue: dist = fl( fl(znorm + cnorm) - fl(2*dot) )
        float4 cn4 = *(const float4*)(g_cnorm + cbase + (tx << 2));
        float cna[4] = {cn4.x, cn4.y, cn4.z, cn4.w};
        #pragma unroll
        for (int c = 0; c < 4; c++) {
            int code = cbase + (tx << 2) + c;
            #pragma unroll
            for (int rp = 0; rp < 2; rp++) {
                float dlo, dhi;
                unpack2(acc[rp][c], dlo, dhi);
                int r0 = rp * 2, r1 = rp * 2 + 1;
                float t0 = __fadd_rn(zn[r0], cna[c]);
                float d0 = __fsub_rn(t0, __fmul_rn(2.0f, dlo));
                if (d0 < minval[r0]) { minval[r0] = d0; minidx[r0] = code; }
                float t1 = __fadd_rn(zn[r1], cna[c]);
                float d1 = __fsub_rn(t1, __fmul_rn(2.0f, dhi));
                if (d1 < minval[r1]) { minval[r1] = d1; minidx[r1] = code; }
            }
        }
        __syncthreads();
    }

    // ---- cross-lane reduction over the 16 code-lanes (same ty group) ----
    #pragma unroll
    for (int r = 0; r < 4; r++) {
        #pragma unroll
        for (int m = 8; m >= 1; m >>= 1) {
            float ov = __shfl_xor_sync(0xffffffffu, minval[r], m);
            int   oi = __shfl_xor_sync(0xffffffffu, minidx[r], m);
            if (ov < minval[r] || (ov == minval[r] && oi < minidx[r])) {
                minval[r] = ov; minidx[r] = oi;
            }
        }
    }

    if (tx == 0) {
        float s = 0.0f;
        #pragma unroll
        for (int r = 0; r < 4; r++) {
            ridx_s[(ty << 2) + r] = minidx[r];
            s = __fadd_rn(s, minval[r]);   // = ||z_r - c_idx||^2
        }
        lsum_s[ty] = s;
    }
    __syncthreads();

    // ---- fused loss: deterministic fixed-point atomic + ticket finalize ----
    if (tid == 0) {
        float s = 0.0f;
        #pragma unroll
        for (int i = 0; i < 16; i++) s = __fadd_rn(s, lsum_s[i]);
        // exact conversion: double mul by 2^20, round to integer
        ull q = (ull)__double2ll_rn((double)s * 1048576.0);
        atomicAdd(&g_loss_acc, q);
        __threadfence();
        unsigned int ticket = atomicAdd(&g_ticket, 1u);
        if (ticket == NBLOCKS - 1) {
            ull tot = atomicAdd(&g_loss_acc, 0ULL);   // coherent read
            double sum = (double)tot * (1.0 / 1048576.0);
            float mean = (float)(sum / (double)(NROWS * DIM));
            out[NROWS * DIM] = __fadd_rn(mean, __fmul_rn(0.25f, mean));
            // reset for next graph replay (stream-ordered visibility)
            g_loss_acc = 0ULL;
            g_ticket   = 0u;
            __threadfence();
        }
    }

    // ---- write indices (as float) ----
    if (tid < TM) {
        out[NROWS * DIM + 1 + rowBase + tid] = (float)ridx_s[tid];
    }

    // ---- write z_q = codebook[idx] (coalesced) ----
    #pragma unroll
    for (int i = 0; i < 16; i++) {
        int flat = i * NTHREADS + tid;
        int r = flat >> 6, c = flat & 63;
        out[(rowBase + r) * DIM + c] = codebook[ridx_s[r] * DIM + c];
    }
}

extern "C" void kernel_launch(void* const* d_in, const int* in_sizes, int n_in,
                              void* d_out, int out_size) {
    const float* z        = (const float*)d_in[0];
    const float* codebook = (const float*)d_in[1];
    float* out = (float*)d_out;

    cnorm_kernel<<<KCODES / 64, 64>>>(codebook);
    vq_kernel<<<NBLOCKS, NTHREADS>>>(z, codebook, out);
}

// round 15
// speedup vs baseline: 1.1166x; 1.1166x over previous
#include <cuda_runtime.h>

// VectorQuantizer: z [32768, 64] fp32, codebook [1024, 64] fp32.
// Outputs (float32, concatenated): z_q (2097152) | loss (1) | indices (32768).
//
// d2_k = fl( fl(znorm + cnorm_k) - fl(2 * dot_k) )  -- replicates reference
// rounding composition so argmin matches jnp.argmin (first-min tie-break).
//
// R15 change (evidence: vq ncu L1=75% > fma=43% -> L1TEX-bound; tile loader's
// 4-way-conflicted transposed STS + scalar LDG = ~30% of L1 traffic):
// codebook is transposed ONCE into g_cbT[d][code] by the prep kernel; the vq
// tile loader becomes coalesced float4 LDG + conflict-free float4 STS into
// the SAME csT layout the k-loop already reads. k-loop/epilogue byte-identical
// to the 137us kernel; numerics bit-exact.

#define NROWS    32768
#define DIM      64
#define KCODES   1024
#define TM       64          // rows per block
#define TN       64          // codes per tile
#define NTILES   (KCODES / TN)
#define NTHREADS 256
#define NBLOCKS  (NROWS / TM)
#define ZS       68          // smem stride (floats), mult of 4 for float4 align
#define CS       68

typedef unsigned long long ull;

__device__ __align__(16) float g_cnorm[KCODES];
__device__ __align__(16) float g_cbT[DIM * KCODES];   // transposed codebook
__device__ ull          g_loss_acc = 0ULL;   // fixed-point sum, 2^20 scale
__device__ unsigned int g_ticket   = 0u;     // completion ticket

__device__ __forceinline__ ull pack2dup(float x) {
    ull r; asm("mov.b64 %0, {%1, %1};" : "=l"(r) : "f"(x)); return r;
}
__device__ __forceinline__ void fma2(ull& acc, ull a, ull b) {
    asm("fma.rn.f32x2 %0, %1, %2, %0;" : "+l"(acc) : "l"(a), "l"(b));
}
__device__ __forceinline__ void unpack2(ull v, float& lo, float& hi) {
    asm("mov.b64 {%0, %1}, %2;" : "=f"(lo), "=f"(hi) : "l"(v));
}

// ---------------------------------------------------------------------------
// Kernel 1: codebook row norms + global transpose.
// Thread k: MLP-16 float4 loads of its row; sequential fp32 adds ascending
// (same rounding as square-then-sum reference); then 64 warp-coalesced
// scattered stores build g_cbT[d][k] (bit-exact copy).
// ---------------------------------------------------------------------------
__global__ void cnorm_kernel(const float* __restrict__ cb) {
    int k = blockIdx.x * 64 + threadIdx.x;
    const float4* row = (const float4*)(cb + k * DIM);
    float4 v[16];
#pragma unroll
    for (int i = 0; i < 16; i++) v[i] = __ldg(row + i);
    float s = 0.0f;
#pragma unroll
    for (int i = 0; i < 16; i++) {
        s = __fadd_rn(s, __fmul_rn(v[i].x, v[i].x));
        s = __fadd_rn(s, __fmul_rn(v[i].y, v[i].y));
        s = __fadd_rn(s, __fmul_rn(v[i].z, v[i].z));
        s = __fadd_rn(s, __fmul_rn(v[i].w, v[i].w));
    }
    g_cnorm[k] = s;
    // transpose: g_cbT[d * KCODES + k] = cb[k][d]; lanes k consecutive ->
    // 128B-coalesced STG per dim.
#pragma unroll
    for (int i = 0; i < 16; i++) {
        g_cbT[(4 * i + 0) * KCODES + k] = v[i].x;
        g_cbT[(4 * i + 1) * KCODES + k] = v[i].y;
        g_cbT[(4 * i + 2) * KCODES + k] = v[i].z;
        g_cbT[(4 * i + 3) * KCODES + k] = v[i].w;
    }
}

// ---------------------------------------------------------------------------
// Kernel 2: main VQ. Each block: 64 rows x 1024 codes. Thread (tx, ty):
// rows ty*4..ty*4+3, codes {tile*64 + tx*4 + 0..3}. f32x2 packed FMA:
// z row-pairs native in transposed smem; c duplicated via pack2dup.
// Tile loader: float4 rows of g_cbT -> float4 STS into csT[d][cl] (CS=68),
// coalesced + conflict-free; prefetched one tile ahead.
// Tail: deterministic fixed-point loss accumulation + ticket finalizer.
// ---------------------------------------------------------------------------
__global__ __launch_bounds__(NTHREADS, 4)
void vq_kernel(const float* __restrict__ z,
               const float* __restrict__ codebook,
               float* __restrict__ out) {
    __shared__ float zsT[DIM * ZS];     // zsT[d][r]
    __shared__ float csT[DIM * CS];     // csT[d][c_local]
    __shared__ float znorm_s[TM];
    __shared__ int   ridx_s[TM];
    __shared__ float lsum_s[16];

    const int tid = threadIdx.x;
    const int tx = tid & 15;            // code group
    const int ty = tid >> 4;            // row group
    const int rowBase = blockIdx.x * TM;

    // loader coordinates: thread owns code-quad jj of dims {16p + dg}
    const int jj = tid & 15;            // code quad within tile (4*jj..4*jj+3)
    const int dg = tid >> 4;            // dim within group of 16

    // ---- load z tile (coalesced), store transposed ----
    #pragma unroll
    for (int i = 0; i < 16; i++) {
        int flat = i * NTHREADS + tid;
        int r = flat >> 6, d = flat & 63;
        zsT[d * ZS + r] = z[(rowBase + r) * DIM + d];
    }

    // ---- prefetch code tile 0 (transposed rows, coalesced float4) ----
    float4 pf[4];
    #pragma unroll
    for (int p = 0; p < 4; p++)
        pf[p] = __ldg((const float4*)(g_cbT + (p * 16 + dg) * KCODES) + jj);

    __syncthreads();

    // ---- row norms: square (rounded) then sequential add ----
    if (tid < TM) {
        float s = 0.0f;
        #pragma unroll
        for (int k = 0; k < DIM; k++) {
            float v = zsT[k * ZS + tid];
            s = __fadd_rn(s, __fmul_rn(v, v));
        }
        znorm_s[tid] = s;
    }
    __syncthreads();

    float zn[4];
    #pragma unroll
    for (int r = 0; r < 4; r++) zn[r] = znorm_s[(ty << 2) + r];

    float minval[4] = {3.4e38f, 3.4e38f, 3.4e38f, 3.4e38f};
    int   minidx[4] = {0, 0, 0, 0};

    for (int t = 0; t < NTILES; t++) {
        const int cbase = t * TN;

        // ---- store prefetched tile: conflict-free float4 STS ----
        #pragma unroll
        for (int p = 0; p < 4; p++)
            *(float4*)(csT + (p * 16 + dg) * CS + 4 * jj) = pf[p];
        __syncthreads();

        // ---- issue next tile's loads; consumed after the k-loop ----
        if (t + 1 < NTILES) {
            const float4* src = (const float4*)(g_cbT + cbase + TN);
            #pragma unroll
            for (int p = 0; p < 4; p++)
                pf[p] = __ldg(src + (p * 16 + dg) * (KCODES / 4) + jj);
        }

        // acc[rp][c]: rp=0 -> rows (0,1) packed, rp=1 -> rows (2,3) packed
        ull acc[2][4];
        #pragma unroll
        for (int rp = 0; rp < 2; rp++)
            #pragma unroll
            for (int c = 0; c < 4; c++) acc[rp][c] = 0ull;  // {0.f, 0.f}

        #pragma unroll 8
        for (int k = 0; k < DIM; k++) {
            const ull* zp = (const ull*)&zsT[k * ZS + (ty << 2)];
            ull z01 = zp[0];           // {z[row0], z[row1]}
            ull z23 = zp[1];           // {z[row2], z[row3]}
            float4 cv = *(const float4*)&csT[k * CS + (tx << 2)];
            ull c0 = pack2dup(cv.x);
            ull c1 = pack2dup(cv.y);
            ull c2 = pack2dup(cv.z);
            ull c3 = pack2dup(cv.w);
            fma2(acc[0][0], z01, c0); fma2(acc[1][0], z23, c0);
            fma2(acc[0][1], z01, c1); fma2(acc[1][1], z23, c1);
            fma2(acc[0][2], z01, c2); fma2(acc[1][2], z23, c2);
            fma2(acc[0][3], z01, c3); fma2(acc[1][3], z23, c3);
        }

        // epilogue: dist = fl( fl(znorm + cnorm) - fl(2*dot) )
        float4 cn4 = *(const float4*)(g_cnorm + cbase + (tx << 2));
        float cna[4] = {cn4.x, cn4.y, cn4.z, cn4.w};
        #pragma unroll
        for (int c = 0; c < 4; c++) {
            int code = cbase + (tx << 2) + c;
            #pragma unroll
            for (int rp = 0; rp < 2; rp++) {
                float dlo, dhi;
                unpack2(acc[rp][c], dlo, dhi);
                int r0 = rp * 2, r1 = rp * 2 + 1;
                float t0 = __fadd_rn(zn[r0], cna[c]);
                float d0 = __fsub_rn(t0, __fmul_rn(2.0f, dlo));
                if (d0 < minval[r0]) { minval[r0] = d0; minidx[r0] = code; }
                float t1 = __fadd_rn(zn[r1], cna[c]);
                float d1 = __fsub_rn(t1, __fmul_rn(2.0f, dhi));
                if (d1 < minval[r1]) { minval[r1] = d1; minidx[r1] = code; }
            }
        }
        __syncthreads();
    }

    // ---- cross-lane reduction over the 16 code-lanes (same ty group) ----
    #pragma unroll
    for (int r = 0; r < 4; r++) {
        #pragma unroll
        for (int m = 8; m >= 1; m >>= 1) {
            float ov = __shfl_xor_sync(0xffffffffu, minval[r], m);
            int   oi = __shfl_xor_sync(0xffffffffu, minidx[r], m);
            if (ov < minval[r] || (ov == minval[r] && oi < minidx[r])) {
                minval[r] = ov; minidx[r] = oi;
            }
        }
    }

    if (tx == 0) {
        float s = 0.0f;
        #pragma unroll
        for (int r = 0; r < 4; r++) {
            ridx_s[(ty << 2) + r] = minidx[r];
            s = __fadd_rn(s, minval[r]);   // = ||z_r - c_idx||^2
        }
        lsum_s[ty] = s;
    }
    __syncthreads();

    // ---- fused loss: deterministic fixed-point atomic + ticket finalize ----
    if (tid == 0) {
        float s = 0.0f;
        #pragma unroll
        for (int i = 0; i < 16; i++) s = __fadd_rn(s, lsum_s[i]);
        ull q = (ull)__double2ll_rn((double)s * 1048576.0);
        atomicAdd(&g_loss_acc, q);
        __threadfence();
        unsigned int ticket = atomicAdd(&g_ticket, 1u);
        if (ticket == NBLOCKS - 1) {
            ull tot = atomicAdd(&g_loss_acc, 0ULL);   // coherent read
            double sum = (double)tot * (1.0 / 1048576.0);
            float mean = (float)(sum / (double)(NROWS * DIM));
            out[NROWS * DIM] = __fadd_rn(mean, __fmul_rn(0.25f, mean));
            g_loss_acc = 0ULL;     // reset for next graph replay
            g_ticket   = 0u;
            __threadfence();
        }
    }

    // ---- write indices (as float) ----
    if (tid < TM) {
        out[NROWS * DIM + 1 + rowBase + tid] = (float)ridx_s[tid];
    }

    // ---- write z_q = codebook[idx] (coalesced) ----
    #pragma unroll
    for (int i = 0; i < 16; i++) {
        int flat = i * NTHREADS + tid;
        int r = flat >> 6, c = flat & 63;
        out[(rowBase + r) * DIM + c] = codebook[ridx_s[r] * DIM + c];
    }
}

extern "C" void kernel_launch(void* const* d_in, const int* in_sizes, int n_in,
                              void* d_out, int out_size) {
    const float* z        = (const float*)d_in[0];
    const float* codebook = (const float*)d_in[1];
    float* out = (float*)d_out;

    cnorm_kernel<<<KCODES / 64, 64>>>(codebook);
    vq_kernel<<<NBLOCKS, NTHREADS>>>(z, codebook, out);
}